// round 9
// baseline (speedup 1.0000x reference)
#include <cuda_runtime.h>

// Problem constants
#define BB 8
#define NN 5000
#define EE 40000
#define FF 64
#define FEE 16
#define FIL 96
#define BN (BB*NN)      // 40000
#define BE (BB*EE)      // 320000
#define UPD_ELEMS (BN*FIL)   // 3,840,000
#define MSG_ELEMS (BE*FIL)   // 30,720,000
#define LN_EPS 1e-3f
#define SCAN_BLK 1024
#define NSCAN ((BN + SCAN_BLK - 1) / SCAN_BLK)   // 40 blocks

// Scratch (device globals: allocation-free per harness rules)
__device__ __align__(16) float g_Pa[UPD_ELEMS];   // nodes @ Wm[0:64]
__device__ __align__(16) float g_Pb[UPD_ELEMS];   // nodes @ Wm[64:128]
__device__ __align__(16) float g_agg[UPD_ELEMS];  // segment-sum of messages
__device__ int g_cnt[BN];        // per-node incoming-edge count
__device__ int g_off[BN + 1];    // CSR offsets
__device__ int g_slot[BE];       // per-edge slot within its node's list
__device__ int g_esrc[BE];       // CSR src list
__device__ int g_eid[BE];        // CSR edge id list
__device__ int g_bsum[NSCAN];    // per-block sums for hierarchical scan

__device__ __forceinline__ float warp_sum(float v) {
#pragma unroll
    for (int o = 16; o; o >>= 1) v += __shfl_xor_sync(0xffffffffu, v, o);
    return v;
}
__device__ __forceinline__ int warp_sum_i(int v) {
#pragma unroll
    for (int o = 16; o; o >>= 1) v += __shfl_xor_sync(0xffffffffu, v, o);
    return v;
}

// ---------------------------------------------------------------------------
// CSR step 2: count incoming edges per node, record slot.
// ---------------------------------------------------------------------------
__global__ __launch_bounds__(256) void count_kernel(const int* __restrict__ edges) {
    int e = blockIdx.x * 256 + threadIdx.x;   // BE divisible by 256
    int2 e2 = ((const int2*)edges)[e];
    int node = (e / EE) * NN + e2.y;          // batch * NN + dst
    g_slot[e] = atomicAdd(&g_cnt[node], 1);
}

// ---------------------------------------------------------------------------
// CSR step 3a: per-block scan of g_cnt -> block-local offsets + block sums.
// ---------------------------------------------------------------------------
__global__ __launch_bounds__(SCAN_BLK) void scan_local_kernel() {
    __shared__ int wsum[32];
    int tid = threadIdx.x, lane = tid & 31, wid = tid >> 5;
    int i = blockIdx.x * SCAN_BLK + tid;
    int v = (i < BN) ? g_cnt[i] : 0;
    int incl = v;
#pragma unroll
    for (int d = 1; d < 32; d <<= 1) {
        int t = __shfl_up_sync(0xffffffffu, incl, d);
        if (lane >= d) incl += t;
    }
    if (lane == 31) wsum[wid] = incl;
    __syncthreads();
    if (wid == 0) {
        int w = wsum[lane];
        int ws = w;
#pragma unroll
        for (int d = 1; d < 32; d <<= 1) {
            int t = __shfl_up_sync(0xffffffffu, ws, d);
            if (lane >= d) ws += t;
        }
        wsum[lane] = ws - w;
        if (lane == 31) g_bsum[blockIdx.x] = ws;
    }
    __syncthreads();
    if (i < BN) g_off[i] = wsum[wid] + (incl - v);   // block-local exclusive
}

// ---------------------------------------------------------------------------
// CSR step 3b (merged): block base = sum(g_bsum[0..bid)), then add.
// ---------------------------------------------------------------------------
__global__ __launch_bounds__(SCAN_BLK) void scan_add_kernel() {
    __shared__ int s_base;
    int tid = threadIdx.x;
    if (tid < 32) {
        int v = 0;
        for (int j = tid; j < blockIdx.x; j += 32) v += g_bsum[j];
        v = warp_sum_i(v);
        if (tid == 0) s_base = v;
    }
    __syncthreads();
    int i = blockIdx.x * SCAN_BLK + tid;
    if (i < BN) g_off[i] += s_base;
    if (blockIdx.x == gridDim.x - 1 && tid == 0) g_off[BN] = BE;
}

// ---------------------------------------------------------------------------
// CSR step 4: scatter edge ids + src into per-node lists.
// ---------------------------------------------------------------------------
__global__ __launch_bounds__(256) void scatter_kernel(const int* __restrict__ edges) {
    int e = blockIdx.x * 256 + threadIdx.x;
    int2 e2 = ((const int2*)edges)[e];
    int node = (e / EE) * NN + e2.y;
    int p = g_off[node] + g_slot[e];
    g_eid[p] = e;
    g_esrc[p] = e2.x;
}

// ---------------------------------------------------------------------------
// K1: Pa|Pb = nodes(40000x64) @ [Wm[0:64] | Wm[64:128]] (64x192)  (R8 version)
// ---------------------------------------------------------------------------
__global__ __launch_bounds__(256) void precompute_kernel(
    const float* __restrict__ nodes, const float* __restrict__ Wm) {
    __shared__ __align__(16) float Xs[64][32];
    __shared__ __align__(16) float Wt4[8][192][4];   // [k4][c][kk]

    int tid = threadIdx.x;
    int tx = tid & 31, ty = tid >> 5;
    int row0 = blockIdx.x * 64;

    float acc[8][6];
#pragma unroll
    for (int i = 0; i < 8; i++)
#pragma unroll
        for (int j = 0; j < 6; j++) acc[i][j] = 0.0f;

    for (int t = 0; t < 2; t++) {
        __syncthreads();
#pragma unroll
        for (int it = 0; it < 24; it++) {
            int idx = tid + 256 * it;
            int k = idx / 192, c = idx % 192;
            float v = (c < 96) ? Wm[(t * 32 + k) * FIL + c]
                               : Wm[(64 + t * 32 + k) * FIL + (c - 96)];
            Wt4[k >> 2][c][k & 3] = v;
        }
#pragma unroll
        for (int it = 0; it < 2; it++) {
            int idx = tid + 256 * it;
            int r = idx >> 3, c4 = idx & 7;
            ((float4*)&Xs[r][0])[c4] =
                ((const float4*)(nodes + (row0 + r) * FF + t * 32))[c4];
        }
        __syncthreads();
#pragma unroll
        for (int k4 = 0; k4 < 8; k4++) {
            float4 wv[6];
#pragma unroll
            for (int j = 0; j < 6; j++)
                wv[j] = *(const float4*)&Wt4[k4][tx + 32 * j][0];
#pragma unroll
            for (int i = 0; i < 8; i++) {
                float4 xv = *(const float4*)&Xs[ty + 8 * i][4 * k4];
#pragma unroll
                for (int j = 0; j < 6; j++) {
                    acc[i][j] += xv.x * wv[j].x;
                    acc[i][j] += xv.y * wv[j].y;
                    acc[i][j] += xv.z * wv[j].z;
                    acc[i][j] += xv.w * wv[j].w;
                }
            }
        }
    }

#pragma unroll
    for (int i = 0; i < 8; i++) {
        int row = row0 + ty + 8 * i;
#pragma unroll
        for (int j = 0; j < 6; j++) {
            int c = tx + 32 * j;
            if (c < 96) g_Pa[row * FIL + c] = acc[i][j];
            else        g_Pb[row * FIL + (c - 96)] = acc[i][j];
        }
    }
}

// ---------------------------------------------------------------------------
// K2 v2: HALF-WARP per edge. Warp owns one node (Pb + bias preloaded into
// registers, channels c = hl + 16*i per lane); each 16-lane half processes
// one incoming edge per iteration: ef@WmC via width-16 shfl + LDS.128 from
// transposed WmCT (pad 20), width-16 LN, register accumulate; cross-half
// merge once per node. No atomics, no per-edge param loads.
// ---------------------------------------------------------------------------
__global__ __launch_bounds__(256) void node_msg_kernel(
    const float* __restrict__ ef, const float* __restrict__ Wm,
    const float* __restrict__ bm, const float* __restrict__ gamma,
    const float* __restrict__ beta, float* __restrict__ msg_out) {
    __shared__ __align__(16) float WmCT[96][20];   // [c][k], pad 20

    int tid = threadIdx.x;
    // Load Wm rows 128..143 transposed: coalesced gmem, scattered STS.
    for (int i = tid; i < 16 * 96; i += 256) {
        int k = i / 96, c = i % 96;
        WmCT[c][k] = Wm[(128 + k) * FIL + c];
    }
    __syncthreads();

    int warp = tid >> 5, lane = tid & 31;
    int half = lane >> 4, hl = lane & 15;
    unsigned hmask = half ? 0xffff0000u : 0x0000ffffu;

    int v = blockIdx.x * 8 + warp;   // BN divisible by 8
    int base = (v / NN) * NN;        // batch * NN

    int beg = g_off[v], end = g_off[v + 1];

    // Per-lane channel set: c_i = hl + 16*i, i = 0..5. Preload params.
    float pbb[6], gr[6], br[6], acc[6];
#pragma unroll
    for (int i = 0; i < 6; i++) {
        int c = hl + 16 * i;
        pbb[i] = g_Pb[v * FIL + c] + bm[c];   // Pb + bias, fused per node
        gr[i] = gamma[c];
        br[i] = beta[c];
        acc[i] = 0.0f;
    }

    for (int c0 = beg; c0 < end; c0 += 2) {
        int epos = c0 + half;
        if (epos < end) {
            int ej   = g_eid[epos];    // uniform within half
            int srcj = g_esrc[epos];

            float efv = ef[ej * FEE + hl];   // 16 floats, coalesced 64B

            float a[6];
#pragma unroll
            for (int i = 0; i < 6; i++) a[i] = pbb[i];

#pragma unroll
            for (int k4 = 0; k4 < 4; k4++) {
                float x0 = __shfl_sync(hmask, efv, 4 * k4 + 0, 16);
                float x1 = __shfl_sync(hmask, efv, 4 * k4 + 1, 16);
                float x2 = __shfl_sync(hmask, efv, 4 * k4 + 2, 16);
                float x3 = __shfl_sync(hmask, efv, 4 * k4 + 3, 16);
#pragma unroll
                for (int i = 0; i < 6; i++) {
                    float4 w = *(const float4*)&WmCT[hl + 16 * i][4 * k4];
                    a[i] += x0 * w.x + x1 * w.y + x2 * w.z + x3 * w.w;
                }
            }

            int pa_off = (base + srcj) * FIL;
#pragma unroll
            for (int i = 0; i < 6; i++)
                a[i] = fmaxf(a[i] + g_Pa[pa_off + hl + 16 * i], 0.0f);

            // LayerNorm over 96 channels, width-16 reductions.
            float s = a[0] + a[1] + a[2] + a[3] + a[4] + a[5];
#pragma unroll
            for (int o = 8; o; o >>= 1) s += __shfl_xor_sync(hmask, s, o, 16);
            float mean = s * (1.0f / 96.0f);

            float d[6], sq = 0.0f;
#pragma unroll
            for (int i = 0; i < 6; i++) { d[i] = a[i] - mean; sq += d[i] * d[i]; }
#pragma unroll
            for (int o = 8; o; o >>= 1) sq += __shfl_xor_sync(hmask, sq, o, 16);
            float inv = rsqrtf(sq * (1.0f / 96.0f) + LN_EPS);

            int mo = ej * FIL + hl;
#pragma unroll
            for (int i = 0; i < 6; i++) {
                float y = d[i] * inv * gr[i] + br[i];
                msg_out[mo + 16 * i] = y;
                acc[i] += y;
            }
        }
    }

    // Merge halves (all lanes converged here) and store aggregate once.
#pragma unroll
    for (int i = 0; i < 6; i++)
        acc[i] += __shfl_xor_sync(0xffffffffu, acc[i], 16);
    if (half == 0) {
#pragma unroll
        for (int i = 0; i < 6; i++)
            g_agg[v * FIL + hl + 16 * i] = acc[i];
    }
}

// ---------------------------------------------------------------------------
// K3: updated = LN(relu([nodes | agg](40000x160) @ Wu(160x96) + bu)) (R8 ver)
// ---------------------------------------------------------------------------
__global__ __launch_bounds__(256) void update_kernel(
    const float* __restrict__ nodes, const float* __restrict__ Wu,
    const float* __restrict__ bu, const float* __restrict__ gamma,
    const float* __restrict__ beta, float* __restrict__ out) {
    __shared__ __align__(16) float Xs[64][32];
    __shared__ __align__(16) float Wt4[8][96][4];   // [k4][c][kk]
    __shared__ float s_bu[96], s_g[96], s_b[96];

    int tid = threadIdx.x;
    int tx = tid & 31, ty = tid >> 5;
    int row0 = blockIdx.x * 64;

    if (tid < 96) { s_bu[tid] = bu[tid]; s_g[tid] = gamma[tid]; s_b[tid] = beta[tid]; }
    __syncthreads();

    float acc[8][3];
#pragma unroll
    for (int i = 0; i < 8; i++) {
        acc[i][0] = s_bu[tx];
        acc[i][1] = s_bu[tx + 32];
        acc[i][2] = s_bu[tx + 64];
    }

    for (int t = 0; t < 5; t++) {
        __syncthreads();
#pragma unroll
        for (int it = 0; it < 12; it++) {
            int idx = tid + 256 * it;
            int k = idx / 96, c = idx % 96;
            Wt4[k >> 2][c][k & 3] = Wu[(t * 32 + k) * FIL + c];
        }
#pragma unroll
        for (int it = 0; it < 2; it++) {
            int idx = tid + 256 * it;
            int r = idx >> 3, c4 = idx & 7;
            float4 v;
            if (t < 2) v = ((const float4*)(nodes + (row0 + r) * FF + t * 32))[c4];
            else       v = ((const float4*)(g_agg + (row0 + r) * FIL + (t - 2) * 32))[c4];
            ((float4*)&Xs[r][0])[c4] = v;
        }
        __syncthreads();
#pragma unroll
        for (int k4 = 0; k4 < 8; k4++) {
            float4 w0 = *(const float4*)&Wt4[k4][tx][0];
            float4 w1 = *(const float4*)&Wt4[k4][tx + 32][0];
            float4 w2 = *(const float4*)&Wt4[k4][tx + 64][0];
#pragma unroll
            for (int i = 0; i < 8; i++) {
                float4 xv = *(const float4*)&Xs[ty + 8 * i][4 * k4];
                acc[i][0] += xv.x * w0.x + xv.y * w0.y + xv.z * w0.z + xv.w * w0.w;
                acc[i][1] += xv.x * w1.x + xv.y * w1.y + xv.z * w1.z + xv.w * w1.w;
                acc[i][2] += xv.x * w2.x + xv.y * w2.y + xv.z * w2.z + xv.w * w2.w;
            }
        }
    }

#pragma unroll
    for (int i = 0; i < 8; i++) {
        int row = row0 + ty + 8 * i;
        float v0 = fmaxf(acc[i][0], 0.0f);
        float v1 = fmaxf(acc[i][1], 0.0f);
        float v2 = fmaxf(acc[i][2], 0.0f);
        float mean = warp_sum(v0 + v1 + v2) * (1.0f / 96.0f);
        float d0 = v0 - mean, d1 = v1 - mean, d2 = v2 - mean;
        float var = warp_sum(d0 * d0 + d1 * d1 + d2 * d2) * (1.0f / 96.0f);
        float inv = rsqrtf(var + LN_EPS);
        int o = row * FIL;
        out[o + tx]      = d0 * inv * s_g[tx]      + s_b[tx];
        out[o + tx + 32] = d1 * inv * s_g[tx + 32] + s_b[tx + 32];
        out[o + tx + 64] = d2 * inv * s_g[tx + 64] + s_b[tx + 64];
    }
}

// ---------------------------------------------------------------------------
// Fork-join resources + g_cnt symbol address (static init; no device allocs).
// ---------------------------------------------------------------------------
static cudaStream_t g_s2;
static cudaEvent_t g_evFork, g_evJoin;
static void* g_cnt_addr;
static struct StreamInit {
    StreamInit() {
        cudaStreamCreateWithFlags(&g_s2, cudaStreamNonBlocking);
        cudaEventCreateWithFlags(&g_evFork, cudaEventDisableTiming);
        cudaEventCreateWithFlags(&g_evJoin, cudaEventDisableTiming);
        cudaGetSymbolAddress(&g_cnt_addr, g_cnt);
    }
} g_streamInit;

// ---------------------------------------------------------------------------
// Launch: [stream0: CSR chain] || [s2: precompute] -> node_msg -> update.
// ---------------------------------------------------------------------------
extern "C" void kernel_launch(void* const* d_in, const int* in_sizes, int n_in,
                              void* d_out, int out_size) {
    const float* nodes = (const float*)d_in[0];
    const float* ef    = (const float*)d_in[1];
    const int*   edges = (const int*)d_in[2];
    const float* Wm    = (const float*)d_in[3];
    const float* bm    = (const float*)d_in[4];
    const float* ln_mg = (const float*)d_in[5];
    const float* ln_mb = (const float*)d_in[6];
    const float* Wu    = (const float*)d_in[7];
    const float* bu    = (const float*)d_in[8];
    const float* ln_ug = (const float*)d_in[9];
    const float* ln_ub = (const float*)d_in[10];

    float* out = (float*)d_out;
    float* upd_out = out;                  // updated_nodes first (tuple order)
    float* msg_out = out + UPD_ELEMS;      // then messages

    // Fork: precompute on side stream, CSR chain on main stream.
    cudaEventRecord(g_evFork, 0);
    cudaStreamWaitEvent(g_s2, g_evFork, 0);
    precompute_kernel<<<BN / 64, 256, 0, g_s2>>>(nodes, Wm);
    cudaEventRecord(g_evJoin, g_s2);

    cudaMemsetAsync(g_cnt_addr, 0, BN * sizeof(int), 0);
    count_kernel<<<BE / 256, 256>>>(edges);
    scan_local_kernel<<<NSCAN, SCAN_BLK>>>();
    scan_add_kernel<<<NSCAN, SCAN_BLK>>>();
    scatter_kernel<<<BE / 256, 256>>>(edges);

    // Join, then dense tail.
    cudaStreamWaitEvent(0, g_evJoin, 0);
    node_msg_kernel<<<BN / 8, 256>>>(ef, Wm, bm, ln_mg, ln_mb, msg_out);
    update_kernel<<<BN / 64, 256>>>(nodes, Wu, bu, ln_ug, ln_ub, upd_out);
}

// round 14
// speedup vs baseline: 1.0405x; 1.0405x over previous
#include <cuda_runtime.h>

// Problem constants
#define BB 8
#define NN 5000
#define EE 40000
#define FF 64
#define FEE 16
#define FIL 96
#define BN (BB*NN)      // 40000
#define BE (BB*EE)      // 320000
#define UPD_ELEMS (BN*FIL)   // 3,840,000
#define MSG_ELEMS (BE*FIL)   // 30,720,000
#define LN_EPS 1e-3f
#define SCAN_BLK 1024
#define NSCAN ((BN + SCAN_BLK - 1) / SCAN_BLK)   // 40 blocks

// Scratch (device globals: allocation-free per harness rules)
__device__ __align__(16) float g_Pa[UPD_ELEMS];   // nodes @ Wm[0:64]
__device__ __align__(16) float g_Pb[UPD_ELEMS];   // nodes @ Wm[64:128]
__device__ __align__(16) float g_agg[UPD_ELEMS];  // segment-sum of messages
__device__ int g_cnt[BN];        // per-node incoming-edge count
__device__ int g_off[BN + 1];    // CSR offsets
__device__ int g_slot[BE];       // per-edge slot within its node's list
__device__ int g_esrc[BE];       // CSR src list
__device__ int g_eid[BE];        // CSR edge id list
__device__ int g_bsum[NSCAN];    // per-block sums for hierarchical scan

__device__ __forceinline__ float warp_sum(float v) {
#pragma unroll
    for (int o = 16; o; o >>= 1) v += __shfl_xor_sync(0xffffffffu, v, o);
    return v;
}
__device__ __forceinline__ int warp_sum_i(int v) {
#pragma unroll
    for (int o = 16; o; o >>= 1) v += __shfl_xor_sync(0xffffffffu, v, o);
    return v;
}

// ---------------------------------------------------------------------------
// CSR step 2: count incoming edges per node, record slot.
// ---------------------------------------------------------------------------
__global__ __launch_bounds__(256) void count_kernel(const int* __restrict__ edges) {
    int e = blockIdx.x * 256 + threadIdx.x;   // BE divisible by 256
    int2 e2 = ((const int2*)edges)[e];
    int node = (e / EE) * NN + e2.y;          // batch * NN + dst
    g_slot[e] = atomicAdd(&g_cnt[node], 1);
}

// ---------------------------------------------------------------------------
// CSR step 3a: per-block scan of g_cnt -> block-local offsets + block sums.
// ---------------------------------------------------------------------------
__global__ __launch_bounds__(SCAN_BLK) void scan_local_kernel() {
    __shared__ int wsum[32];
    int tid = threadIdx.x, lane = tid & 31, wid = tid >> 5;
    int i = blockIdx.x * SCAN_BLK + tid;
    int v = (i < BN) ? g_cnt[i] : 0;
    int incl = v;
#pragma unroll
    for (int d = 1; d < 32; d <<= 1) {
        int t = __shfl_up_sync(0xffffffffu, incl, d);
        if (lane >= d) incl += t;
    }
    if (lane == 31) wsum[wid] = incl;
    __syncthreads();
    if (wid == 0) {
        int w = wsum[lane];
        int ws = w;
#pragma unroll
        for (int d = 1; d < 32; d <<= 1) {
            int t = __shfl_up_sync(0xffffffffu, ws, d);
            if (lane >= d) ws += t;
        }
        wsum[lane] = ws - w;
        if (lane == 31) g_bsum[blockIdx.x] = ws;
    }
    __syncthreads();
    if (i < BN) g_off[i] = wsum[wid] + (incl - v);   // block-local exclusive
}

// ---------------------------------------------------------------------------
// CSR step 3b (merged): block base = sum(g_bsum[0..bid)), then add.
// ---------------------------------------------------------------------------
__global__ __launch_bounds__(SCAN_BLK) void scan_add_kernel() {
    __shared__ int s_base;
    int tid = threadIdx.x;
    if (tid < 32) {
        int v = 0;
        for (int j = tid; j < blockIdx.x; j += 32) v += g_bsum[j];
        v = warp_sum_i(v);
        if (tid == 0) s_base = v;
    }
    __syncthreads();
    int i = blockIdx.x * SCAN_BLK + tid;
    if (i < BN) g_off[i] += s_base;
    if (blockIdx.x == gridDim.x - 1 && tid == 0) g_off[BN] = BE;
}

// ---------------------------------------------------------------------------
// CSR step 4: scatter edge ids + src into per-node lists.
// ---------------------------------------------------------------------------
__global__ __launch_bounds__(256) void scatter_kernel(const int* __restrict__ edges) {
    int e = blockIdx.x * 256 + threadIdx.x;
    int2 e2 = ((const int2*)edges)[e];
    int node = (e / EE) * NN + e2.y;
    int p = g_off[node] + g_slot[e];
    g_eid[p] = e;
    g_esrc[p] = e2.x;
}

// ---------------------------------------------------------------------------
// K1: Pa|Pb = nodes(40000x64) @ [Wm[0:64] | Wm[64:128]] (64x192)  (R8 version)
// ---------------------------------------------------------------------------
__global__ __launch_bounds__(256) void precompute_kernel(
    const float* __restrict__ nodes, const float* __restrict__ Wm) {
    __shared__ __align__(16) float Xs[64][32];
    __shared__ __align__(16) float Wt4[8][192][4];   // [k4][c][kk]

    int tid = threadIdx.x;
    int tx = tid & 31, ty = tid >> 5;
    int row0 = blockIdx.x * 64;

    float acc[8][6];
#pragma unroll
    for (int i = 0; i < 8; i++)
#pragma unroll
        for (int j = 0; j < 6; j++) acc[i][j] = 0.0f;

    for (int t = 0; t < 2; t++) {
        __syncthreads();
#pragma unroll
        for (int it = 0; it < 24; it++) {
            int idx = tid + 256 * it;
            int k = idx / 192, c = idx % 192;
            float v = (c < 96) ? Wm[(t * 32 + k) * FIL + c]
                               : Wm[(64 + t * 32 + k) * FIL + (c - 96)];
            Wt4[k >> 2][c][k & 3] = v;
        }
#pragma unroll
        for (int it = 0; it < 2; it++) {
            int idx = tid + 256 * it;
            int r = idx >> 3, c4 = idx & 7;
            ((float4*)&Xs[r][0])[c4] =
                ((const float4*)(nodes + (row0 + r) * FF + t * 32))[c4];
        }
        __syncthreads();
#pragma unroll
        for (int k4 = 0; k4 < 8; k4++) {
            float4 wv[6];
#pragma unroll
            for (int j = 0; j < 6; j++)
                wv[j] = *(const float4*)&Wt4[k4][tx + 32 * j][0];
#pragma unroll
            for (int i = 0; i < 8; i++) {
                float4 xv = *(const float4*)&Xs[ty + 8 * i][4 * k4];
#pragma unroll
                for (int j = 0; j < 6; j++) {
                    acc[i][j] += xv.x * wv[j].x;
                    acc[i][j] += xv.y * wv[j].y;
                    acc[i][j] += xv.z * wv[j].z;
                    acc[i][j] += xv.w * wv[j].w;
                }
            }
        }
    }

#pragma unroll
    for (int i = 0; i < 8; i++) {
        int row = row0 + ty + 8 * i;
#pragma unroll
        for (int j = 0; j < 6; j++) {
            int c = tx + 32 * j;
            if (c < 96) g_Pa[row * FIL + c] = acc[i][j];
            else        g_Pb[row * FIL + (c - 96)] = acc[i][j];
        }
    }
}

// ---------------------------------------------------------------------------
// K2 v3: warp per node (R7 structure) + three latency attacks:
//  - WmC held in registers (16x3 per lane), zero LDS in the edge loop
//  - 1-deep software pipeline: next edge's ef + Pa prefetched during compute
//  - fused mean/var butterfly (one reduction tree instead of two)
// No atomics.
// ---------------------------------------------------------------------------
__global__ __launch_bounds__(256) void node_msg_kernel(
    const float* __restrict__ ef, const float* __restrict__ Wm,
    const float* __restrict__ bm, const float* __restrict__ gamma,
    const float* __restrict__ beta, float* __restrict__ msg_out) {
    int tid = threadIdx.x;
    int warp = tid >> 5, lane = tid & 31;
    int v = blockIdx.x * 8 + warp;   // BN divisible by 8
    int base = (v / NN) * NN;        // batch * NN

    // WmC (Wm rows 128..143) in registers: wmc[k][i] for channels lane+32i.
    float wmc[16][3];
#pragma unroll
    for (int k = 0; k < 16; k++) {
        const float* r = Wm + (128 + k) * FIL + lane;
        wmc[k][0] = r[0];
        wmc[k][1] = r[32];
        wmc[k][2] = r[64];
    }

    // Per-node constants: bias + Pb fused; gamma/beta.
    float b0 = bm[lane]      + g_Pb[v * FIL + lane];
    float b1 = bm[lane + 32] + g_Pb[v * FIL + lane + 32];
    float b2 = bm[lane + 64] + g_Pb[v * FIL + lane + 64];
    float g0 = gamma[lane], g1 = gamma[lane + 32], g2 = gamma[lane + 64];
    float be0 = beta[lane], be1 = beta[lane + 32], be2 = beta[lane + 64];

    int beg = g_off[v], end = g_off[v + 1];
    float acc0 = 0.f, acc1 = 0.f, acc2 = 0.f;

    for (int c0 = beg; c0 < end; c0 += 32) {
        int m = min(32, end - c0);
        int e_l   = (lane < m) ? g_eid[c0 + lane]  : 0;
        int src_l = (lane < m) ? g_esrc[c0 + lane] : 0;

        // Prefetch edge 0.
        int ej_n  = __shfl_sync(0xffffffffu, e_l, 0);
        int src_n = __shfl_sync(0xffffffffu, src_l, 0);
        float efv_n = (lane < 16) ? ef[ej_n * FEE + lane] : 0.0f;
        int pan = (base + src_n) * FIL;
        float pa0_n = g_Pa[pan + lane];
        float pa1_n = g_Pa[pan + lane + 32];
        float pa2_n = g_Pa[pan + lane + 64];

        for (int j = 0; j < m; j++) {
            int ej = ej_n;
            float efv = efv_n, pa0 = pa0_n, pa1 = pa1_n, pa2 = pa2_n;
            if (j + 1 < m) {   // prefetch next edge while computing this one
                ej_n  = __shfl_sync(0xffffffffu, e_l, j + 1);
                int s2 = __shfl_sync(0xffffffffu, src_l, j + 1);
                efv_n = (lane < 16) ? ef[ej_n * FEE + lane] : 0.0f;
                int pn = (base + s2) * FIL;
                pa0_n = g_Pa[pn + lane];
                pa1_n = g_Pa[pn + lane + 32];
                pa2_n = g_Pa[pn + lane + 64];
            }

            float a0 = b0 + pa0, a1 = b1 + pa1, a2 = b2 + pa2;
#pragma unroll
            for (int k = 0; k < 16; k++) {
                float x = __shfl_sync(0xffffffffu, efv, k);
                a0 += x * wmc[k][0];
                a1 += x * wmc[k][1];
                a2 += x * wmc[k][2];
            }

            a0 = fmaxf(a0, 0.0f); a1 = fmaxf(a1, 0.0f); a2 = fmaxf(a2, 0.0f);

            // Fused LN statistics: one butterfly for (sum, sumsq).
            float s = a0 + a1 + a2;
            float q = a0 * a0 + a1 * a1 + a2 * a2;
#pragma unroll
            for (int o = 16; o; o >>= 1) {
                s += __shfl_xor_sync(0xffffffffu, s, o);
                q += __shfl_xor_sync(0xffffffffu, q, o);
            }
            float mean = s * (1.0f / 96.0f);
            float var = q * (1.0f / 96.0f) - mean * mean;
            float inv = rsqrtf(var + LN_EPS);

            float y0 = (a0 - mean) * inv * g0 + be0;
            float y1 = (a1 - mean) * inv * g1 + be1;
            float y2 = (a2 - mean) * inv * g2 + be2;

            int mo = ej * FIL;
            msg_out[mo + lane]      = y0;
            msg_out[mo + lane + 32] = y1;
            msg_out[mo + lane + 64] = y2;

            acc0 += y0; acc1 += y1; acc2 += y2;
        }
    }

    int o = v * FIL;
    g_agg[o + lane]      = acc0;
    g_agg[o + lane + 32] = acc1;
    g_agg[o + lane + 64] = acc2;
}

// ---------------------------------------------------------------------------
// K3: updated = LN(relu([nodes | agg](40000x160) @ Wu(160x96) + bu)) (R8 ver)
// ---------------------------------------------------------------------------
__global__ __launch_bounds__(256) void update_kernel(
    const float* __restrict__ nodes, const float* __restrict__ Wu,
    const float* __restrict__ bu, const float* __restrict__ gamma,
    const float* __restrict__ beta, float* __restrict__ out) {
    __shared__ __align__(16) float Xs[64][32];
    __shared__ __align__(16) float Wt4[8][96][4];   // [k4][c][kk]
    __shared__ float s_bu[96], s_g[96], s_b[96];

    int tid = threadIdx.x;
    int tx = tid & 31, ty = tid >> 5;
    int row0 = blockIdx.x * 64;

    if (tid < 96) { s_bu[tid] = bu[tid]; s_g[tid] = gamma[tid]; s_b[tid] = beta[tid]; }
    __syncthreads();

    float acc[8][3];
#pragma unroll
    for (int i = 0; i < 8; i++) {
        acc[i][0] = s_bu[tx];
        acc[i][1] = s_bu[tx + 32];
        acc[i][2] = s_bu[tx + 64];
    }

    for (int t = 0; t < 5; t++) {
        __syncthreads();
#pragma unroll
        for (int it = 0; it < 12; it++) {
            int idx = tid + 256 * it;
            int k = idx / 96, c = idx % 96;
            Wt4[k >> 2][c][k & 3] = Wu[(t * 32 + k) * FIL + c];
        }
#pragma unroll
        for (int it = 0; it < 2; it++) {
            int idx = tid + 256 * it;
            int r = idx >> 3, c4 = idx & 7;
            float4 v;
            if (t < 2) v = ((const float4*)(nodes + (row0 + r) * FF + t * 32))[c4];
            else       v = ((const float4*)(g_agg + (row0 + r) * FIL + (t - 2) * 32))[c4];
            ((float4*)&Xs[r][0])[c4] = v;
        }
        __syncthreads();
#pragma unroll
        for (int k4 = 0; k4 < 8; k4++) {
            float4 w0 = *(const float4*)&Wt4[k4][tx][0];
            float4 w1 = *(const float4*)&Wt4[k4][tx + 32][0];
            float4 w2 = *(const float4*)&Wt4[k4][tx + 64][0];
#pragma unroll
            for (int i = 0; i < 8; i++) {
                float4 xv = *(const float4*)&Xs[ty + 8 * i][4 * k4];
                acc[i][0] += xv.x * w0.x + xv.y * w0.y + xv.z * w0.z + xv.w * w0.w;
                acc[i][1] += xv.x * w1.x + xv.y * w1.y + xv.z * w1.z + xv.w * w1.w;
                acc[i][2] += xv.x * w2.x + xv.y * w2.y + xv.z * w2.z + xv.w * w2.w;
            }
        }
    }

#pragma unroll
    for (int i = 0; i < 8; i++) {
        int row = row0 + ty + 8 * i;
        float v0 = fmaxf(acc[i][0], 0.0f);
        float v1 = fmaxf(acc[i][1], 0.0f);
        float v2 = fmaxf(acc[i][2], 0.0f);
        float mean = warp_sum(v0 + v1 + v2) * (1.0f / 96.0f);
        float d0 = v0 - mean, d1 = v1 - mean, d2 = v2 - mean;
        float var = warp_sum(d0 * d0 + d1 * d1 + d2 * d2) * (1.0f / 96.0f);
        float inv = rsqrtf(var + LN_EPS);
        int o = row * FIL;
        out[o + tx]      = d0 * inv * s_g[tx]      + s_b[tx];
        out[o + tx + 32] = d1 * inv * s_g[tx + 32] + s_b[tx + 32];
        out[o + tx + 64] = d2 * inv * s_g[tx + 64] + s_b[tx + 64];
    }
}

// ---------------------------------------------------------------------------
// Fork-join resources + g_cnt symbol address (static init; no device allocs).
// ---------------------------------------------------------------------------
static cudaStream_t g_s2;
static cudaEvent_t g_evFork, g_evJoin;
static void* g_cnt_addr;
static struct StreamInit {
    StreamInit() {
        cudaStreamCreateWithFlags(&g_s2, cudaStreamNonBlocking);
        cudaEventCreateWithFlags(&g_evFork, cudaEventDisableTiming);
        cudaEventCreateWithFlags(&g_evJoin, cudaEventDisableTiming);
        cudaGetSymbolAddress(&g_cnt_addr, g_cnt);
    }
} g_streamInit;

// ---------------------------------------------------------------------------
// Launch: [stream0: CSR chain] || [s2: precompute] -> node_msg -> update.
// ---------------------------------------------------------------------------
extern "C" void kernel_launch(void* const* d_in, const int* in_sizes, int n_in,
                              void* d_out, int out_size) {
    const float* nodes = (const float*)d_in[0];
    const float* ef    = (const float*)d_in[1];
    const int*   edges = (const int*)d_in[2];
    const float* Wm    = (const float*)d_in[3];
    const float* bm    = (const float*)d_in[4];
    const float* ln_mg = (const float*)d_in[5];
    const float* ln_mb = (const float*)d_in[6];
    const float* Wu    = (const float*)d_in[7];
    const float* bu    = (const float*)d_in[8];
    const float* ln_ug = (const float*)d_in[9];
    const float* ln_ub = (const float*)d_in[10];

    float* out = (float*)d_out;
    float* upd_out = out;                  // updated_nodes first (tuple order)
    float* msg_out = out + UPD_ELEMS;      // then messages

    // Fork: precompute on side stream, CSR chain on main stream.
    cudaEventRecord(g_evFork, 0);
    cudaStreamWaitEvent(g_s2, g_evFork, 0);
    precompute_kernel<<<BN / 64, 256, 0, g_s2>>>(nodes, Wm);
    cudaEventRecord(g_evJoin, g_s2);

    cudaMemsetAsync(g_cnt_addr, 0, BN * sizeof(int), 0);
    count_kernel<<<BE / 256, 256>>>(edges);
    scan_local_kernel<<<NSCAN, SCAN_BLK>>>();
    scan_add_kernel<<<NSCAN, SCAN_BLK>>>();
    scatter_kernel<<<BE / 256, 256>>>(edges);

    // Join, then dense tail.
    cudaStreamWaitEvent(0, g_evJoin, 0);
    node_msg_kernel<<<BN / 8, 256>>>(ef, Wm, bm, ln_mg, ln_mb, msg_out);
    update_kernel<<<BN / 64, 256>>>(nodes, Wu, bu, ln_ug, ln_ub, upd_out);
}